// round 11
// baseline (speedup 1.0000x reference)
#include <cuda_runtime.h>

// Problem constants (shapes are fixed by the dataset).
#define N_ATOMS_C 20000
#define CAP 96          // per-atom bucket capacity; dataset max degree ~60
#define OVF_CAP 8192
#define MP_SCALING 0.1f

// Scratch: __device__ globals (no allocations allowed; zero-initialized at
// module load). Invariant: g_count/g_ovf_count are 0 on entry to
// kernel_launch and restored to 0 by gather_kernel, so every call does
// identical work.
__device__ int  g_count[N_ATOMS_C];
__device__ int2 g_bucket[N_ATOMS_C * CAP];   // (edge_id, neighbor_id)
__device__ int  g_ovf_count;
__device__ int  g_ovf[OVF_CAP];

__device__ __forceinline__ void scatter_one(int e, int c, int n) {
    int pos = atomicAdd(&g_count[c], 1);
    if (pos < CAP) {
        g_bucket[c * CAP + pos] = make_int2(e, n);
    } else {
        int o = atomicAdd(&g_ovf_count, 1);
        if (o < OVF_CAP) g_ovf[o] = e;
    }
}

// 4 edges per thread: 4 independent atomic->store chains in flight.
__global__ void scatter_kernel(const int* __restrict__ centers,
                               const int* __restrict__ neighbors, int E) {
    int t = blockIdx.x * blockDim.x + threadIdx.x;
    int e = t * 4;
    if (e + 3 < E) {
        int4 c = __ldg((const int4*)(centers + e));
        int4 n = __ldg((const int4*)(neighbors + e));
        scatter_one(e,     c.x, n.x);
        scatter_one(e + 1, c.y, n.y);
        scatter_one(e + 2, c.z, n.z);
        scatter_one(e + 3, c.w, n.w);
    } else {
        for (int j = e; j < E; j++) scatter_one(j, centers[j], neighbors[j]);
    }
}

// Single-edge accumulate (tail / overflow path).
__device__ __forceinline__ void edge_accum(
    float acc[16], int k,
    const float* __restrict__ sh,
    const float* __restrict__ rb,
    const float* __restrict__ emb,
    int e, int n)
{
    const float* rbe = rb + (size_t)e * 128 + k;
    float r0 = __ldcs(rbe), r1 = __ldcs(rbe + 32), r2 = __ldcs(rbe + 64), r3 = __ldcs(rbe + 96);
    float em = __ldg(emb + (size_t)n * 32 + k);
    float sv = (k < 16) ? __ldg(sh + (size_t)e * 16 + k) : 0.0f;
    float t0 = r0 * em, t1 = r1 * em, t2 = r2 * em, t3 = r3 * em;
#pragma unroll
    for (int m = 0; m < 16; m++) {
        float s = __shfl_sync(0xffffffffu, sv, m);
        float t = (m < 1) ? t0 : (m < 4) ? t1 : (m < 9) ? t2 : t3;
        acc[m] = fmaf(s, t, acc[m]);
    }
}

// Full payload of one 4-edge group, register-resident.
struct Grp {
    float r00,r01,r02,r03, r10,r11,r12,r13, r20,r21,r22,r23, r30,r31,r32,r33;
    float em0,em1,em2,em3, svA,svB;
};

__device__ __forceinline__ Grp load_grp(
    const float* __restrict__ rb, const float* __restrict__ emb,
    const float* __restrict__ sh, int4 bA, int4 bB, int k)
{
    Grp G;
    const float* p0 = rb + (size_t)bA.x * 128 + k;
    const float* p1 = rb + (size_t)bA.z * 128 + k;
    const float* p2 = rb + (size_t)bB.x * 128 + k;
    const float* p3 = rb + (size_t)bB.z * 128 + k;
    G.r00=__ldcs(p0); G.r01=__ldcs(p0+32); G.r02=__ldcs(p0+64); G.r03=__ldcs(p0+96);
    G.r10=__ldcs(p1); G.r11=__ldcs(p1+32); G.r12=__ldcs(p1+64); G.r13=__ldcs(p1+96);
    G.r20=__ldcs(p2); G.r21=__ldcs(p2+32); G.r22=__ldcs(p2+64); G.r23=__ldcs(p2+96);
    G.r30=__ldcs(p3); G.r31=__ldcs(p3+32); G.r32=__ldcs(p3+64); G.r33=__ldcs(p3+96);
    G.em0 = __ldg(emb + (size_t)bA.y * 32 + k);
    G.em1 = __ldg(emb + (size_t)bA.w * 32 + k);
    G.em2 = __ldg(emb + (size_t)bB.y * 32 + k);
    G.em3 = __ldg(emb + (size_t)bB.w * 32 + k);
    G.svA = __ldg(sh + ((k < 16) ? (size_t)bA.x * 16 + k
                                 : (size_t)bA.z * 16 + (k - 16)));
    G.svB = __ldg(sh + ((k < 16) ? (size_t)bB.x * 16 + k
                                 : (size_t)bB.z * 16 + (k - 16)));
    return G;
}

__device__ __forceinline__ void compute_grp(float acc[16], const Grp& G)
{
    float t00=G.r00*G.em0, t01=G.r01*G.em0, t02=G.r02*G.em0, t03=G.r03*G.em0;
    float t10=G.r10*G.em1, t11=G.r11*G.em1, t12=G.r12*G.em1, t13=G.r13*G.em1;
    float t20=G.r20*G.em2, t21=G.r21*G.em2, t22=G.r22*G.em2, t23=G.r23*G.em2;
    float t30=G.r30*G.em3, t31=G.r31*G.em3, t32=G.r32*G.em3, t33=G.r33*G.em3;
#pragma unroll
    for (int m = 0; m < 16; m++) {
        float s0 = __shfl_sync(0xffffffffu, G.svA, m);
        float s1 = __shfl_sync(0xffffffffu, G.svA, m + 16);
        float s2 = __shfl_sync(0xffffffffu, G.svB, m);
        float s3 = __shfl_sync(0xffffffffu, G.svB, m + 16);
        float u0 = (m < 1) ? t00 : (m < 4) ? t01 : (m < 9) ? t02 : t03;
        float u1 = (m < 1) ? t10 : (m < 4) ? t11 : (m < 9) ? t12 : t13;
        float u2 = (m < 1) ? t20 : (m < 4) ? t21 : (m < 9) ? t22 : t23;
        float u3 = (m < 1) ? t30 : (m < 4) ? t31 : (m < 9) ? t32 : t33;
        acc[m] = fmaf(s0, u0, acc[m]);
        acc[m] = fmaf(s1, u1, acc[m]);
        acc[m] = fmaf(s2, u2, acc[m]);
        acc[m] = fmaf(s3, u3, acc[m]);
    }
}

// One warp per atom; lane = k. Register software-pipeline: group g+1's 22
// LDGs are issued BEFORE group g's compute phase, so each warp keeps ~22
// loads in flight continuously instead of bursting. Bucket ids stay one
// further step ahead so the g+1 load phase never waits on an L2 round trip.
__global__ __launch_bounds__(128) void gather_kernel(
    const float* __restrict__ sh, const float* __restrict__ rb,
    const float* __restrict__ emb,
    const int* __restrict__ centers, const int* __restrict__ neighbors,
    float* __restrict__ out, int n_atoms)
{
    int a = blockIdx.x * 4 + (threadIdx.x >> 5);
    if (a >= n_atoms) return;
    int k = threadIdx.x & 31;

    int deg_raw = g_count[a];
    int deg = deg_raw > CAP ? CAP : deg_raw;

    float acc[16];
#pragma unroll
    for (int m = 0; m < 16; m++) acc[m] = 0.0f;

    const int2* bk = g_bucket + (size_t)a * CAP;
    int ng = deg >> 2;

    int4 bA = make_int4(0,0,0,0), bB = bA;
    Grp G0, G1;
    if (ng > 0) {
        bA = __ldg((const int4*)bk);
        bB = __ldg((const int4*)(bk + 2));
        G0 = load_grp(rb, emb, sh, bA, bB, k);           // rb(0)
        if (ng > 1) {
            bA = __ldg((const int4*)(bk + 4));           // bkt(1)
            bB = __ldg((const int4*)(bk + 6));
        }
    }

    int g = 0;
    while (g < ng) {
        // even step: stage g+1, compute g (in G0)
        if (g + 1 < ng) {
            G1 = load_grp(rb, emb, sh, bA, bB, k);       // rb(g+1)
            if (g + 2 < ng) {
                bA = __ldg((const int4*)(bk + 4 * (g + 2)));
                bB = __ldg((const int4*)(bk + 4 * (g + 2) + 2));
            }
        }
        compute_grp(acc, G0);
        if (++g >= ng) break;

        // odd step: stage g+1, compute g (in G1)
        if (g + 1 < ng) {
            G0 = load_grp(rb, emb, sh, bA, bB, k);
            if (g + 2 < ng) {
                bA = __ldg((const int4*)(bk + 4 * (g + 2)));
                bB = __ldg((const int4*)(bk + 4 * (g + 2) + 2));
            }
        }
        compute_grp(acc, G1);
        ++g;
    }

    for (int i = ng * 4; i < deg; i++) {                 // tail (<=3 edges)
        int2 en = __ldg(bk + i);
        edge_accum(acc, k, sh, rb, emb, en.x, en.y);
    }

    // Overflow edges for this atom (empty on this dataset: max deg ~60 << CAP).
    if (deg_raw > CAP) {
        int novf = g_ovf_count;
        if (novf > OVF_CAP) novf = OVF_CAP;
        for (int j = 0; j < novf; j++) {
            int e = g_ovf[j];
            if (centers[e] == a) edge_accum(acc, k, sh, rb, emb, e, neighbors[e]);
        }
    }

    // Streaming stores: out is write-once, never re-read.
    float* o = out + (size_t)a * 512 + k;
#pragma unroll
    for (int m = 0; m < 16; m++) __stcs(o + m * 32, acc[m] * MP_SCALING);

    // Restore scratch invariant for the next graph replay.
    if (k == 0) g_count[a] = 0;
    if (a == 0 && k == 0) g_ovf_count = 0;
}

extern "C" void kernel_launch(void* const* d_in, const int* in_sizes, int n_in,
                              void* d_out, int out_size) {
    const float* sh        = (const float*)d_in[0];  // (E, 16)
    const float* rb        = (const float*)d_in[1];  // (E, 4, 32)
    const float* emb       = (const float*)d_in[2];  // (n_atoms, 32)
    const int*   centers   = (const int*)d_in[3];    // (E,)
    const int*   neighbors = (const int*)d_in[4];    // (E,)
    float*       out       = (float*)d_out;          // (n_atoms, 16, 32)

    int E       = in_sizes[0] / 16;
    int n_atoms = in_sizes[2] / 32;

    scatter_kernel<<<(E / 4 + 511) / 512, 512>>>(centers, neighbors, E);
    gather_kernel<<<(n_atoms + 3) / 4, 128>>>(sh, rb, emb, centers, neighbors,
                                              out, n_atoms);
}

// round 12
// speedup vs baseline: 1.0355x; 1.0355x over previous
#include <cuda_runtime.h>

// Problem constants (shapes are fixed by the dataset).
#define N_ATOMS_C 20000
#define CAP 96          // per-atom bucket capacity; dataset max degree ~60
#define OVF_CAP 8192
#define MP_SCALING 0.1f

// Scratch: __device__ globals (no allocations allowed; zero-initialized at
// module load). Invariant: g_count/g_ovf_count are 0 on entry to
// kernel_launch and restored to 0 by gather_kernel; g_next is reset by
// scatter_kernel before gather_kernel consumes it (same stream, ordered).
__device__ int  g_count[N_ATOMS_C];
__device__ int2 g_bucket[N_ATOMS_C * CAP];   // (edge_id, neighbor_id)
__device__ int  g_ovf_count;
__device__ int  g_ovf[OVF_CAP];
__device__ int  g_next;                      // work-stealing cursor

__device__ __forceinline__ void scatter_one(int e, int c, int n) {
    int pos = atomicAdd(&g_count[c], 1);
    if (pos < CAP) {
        g_bucket[c * CAP + pos] = make_int2(e, n);
    } else {
        int o = atomicAdd(&g_ovf_count, 1);
        if (o < OVF_CAP) g_ovf[o] = e;
    }
}

// 4 edges per thread: 4 independent atomic->store chains in flight.
__global__ void scatter_kernel(const int* __restrict__ centers,
                               const int* __restrict__ neighbors, int E) {
    int t = blockIdx.x * blockDim.x + threadIdx.x;
    if (t == 0) g_next = 0;                  // reset gather's work cursor
    int e = t * 4;
    if (e + 3 < E) {
        int4 c = __ldg((const int4*)(centers + e));
        int4 n = __ldg((const int4*)(neighbors + e));
        scatter_one(e,     c.x, n.x);
        scatter_one(e + 1, c.y, n.y);
        scatter_one(e + 2, c.z, n.z);
        scatter_one(e + 3, c.w, n.w);
    } else {
        for (int j = e; j < E; j++) scatter_one(j, centers[j], neighbors[j]);
    }
}

// Single-edge accumulate (tail / overflow path).
__device__ __forceinline__ void edge_accum(
    float acc[16], int k,
    const float* __restrict__ sh,
    const float* __restrict__ rb,
    const float* __restrict__ emb,
    int e, int n)
{
    const float* rbe = rb + (size_t)e * 128 + k;
    float r0 = __ldcs(rbe), r1 = __ldcs(rbe + 32), r2 = __ldcs(rbe + 64), r3 = __ldcs(rbe + 96);
    float em = __ldg(emb + (size_t)n * 32 + k);
    float sv = (k < 16) ? __ldg(sh + (size_t)e * 16 + k) : 0.0f;
    float t0 = r0 * em, t1 = r1 * em, t2 = r2 * em, t3 = r3 * em;
#pragma unroll
    for (int m = 0; m < 16; m++) {
        float s = __shfl_sync(0xffffffffu, sv, m);
        float t = (m < 1) ? t0 : (m < 4) ? t1 : (m < 9) ? t2 : t3;
        acc[m] = fmaf(s, t, acc[m]);
    }
}

// Process one atom with the R10 body (4-edge unroll, bucket prefetch,
// evict-first rb loads, streaming out stores).
__device__ __forceinline__ void process_atom(
    int a, int k,
    const float* __restrict__ sh, const float* __restrict__ rb,
    const float* __restrict__ emb,
    const int* __restrict__ centers, const int* __restrict__ neighbors,
    float* __restrict__ out)
{
    int deg_raw = g_count[a];
    int deg = deg_raw > CAP ? CAP : deg_raw;

    float acc[16];
#pragma unroll
    for (int m = 0; m < 16; m++) acc[m] = 0.0f;

    const int2* bk = g_bucket + (size_t)a * CAP;

    int4 bA = make_int4(0,0,0,0), bB = bA;
    if (deg >= 4) {
        bA = __ldg((const int4*)bk);          // e0,n0,e1,n1
        bB = __ldg((const int4*)(bk + 2));    // e2,n2,e3,n3
    }

    int i = 0;
    for (; i + 4 <= deg; i += 4) {
        // Prefetch next group's bucket entries (L2 hit, hidden under compute).
        int4 nA = bA, nB = bB;
        if (i + 8 <= deg) {
            nA = __ldg((const int4*)(bk + i + 4));
            nB = __ldg((const int4*)(bk + i + 6));
        }

        // ---- front-batched load phase ----
        const float* p0 = rb + (size_t)bA.x * 128 + k;
        const float* p1 = rb + (size_t)bA.z * 128 + k;
        const float* p2 = rb + (size_t)bB.x * 128 + k;
        const float* p3 = rb + (size_t)bB.z * 128 + k;
        float r00=__ldcs(p0), r01=__ldcs(p0+32), r02=__ldcs(p0+64), r03=__ldcs(p0+96);
        float r10=__ldcs(p1), r11=__ldcs(p1+32), r12=__ldcs(p1+64), r13=__ldcs(p1+96);
        float r20=__ldcs(p2), r21=__ldcs(p2+32), r22=__ldcs(p2+64), r23=__ldcs(p2+96);
        float r30=__ldcs(p3), r31=__ldcs(p3+32), r32=__ldcs(p3+64), r33=__ldcs(p3+96);
        float em0 = __ldg(emb + (size_t)bA.y * 32 + k);
        float em1 = __ldg(emb + (size_t)bA.w * 32 + k);
        float em2 = __ldg(emb + (size_t)bB.y * 32 + k);
        float em3 = __ldg(emb + (size_t)bB.w * 32 + k);
        float svA = __ldg(sh + ((k < 16) ? (size_t)bA.x * 16 + k
                                         : (size_t)bA.z * 16 + (k - 16)));
        float svB = __ldg(sh + ((k < 16) ? (size_t)bB.x * 16 + k
                                         : (size_t)bB.z * 16 + (k - 16)));

        // ---- compute phase ----
        float t00=r00*em0, t01=r01*em0, t02=r02*em0, t03=r03*em0;
        float t10=r10*em1, t11=r11*em1, t12=r12*em1, t13=r13*em1;
        float t20=r20*em2, t21=r21*em2, t22=r22*em2, t23=r23*em2;
        float t30=r30*em3, t31=r31*em3, t32=r32*em3, t33=r33*em3;
#pragma unroll
        for (int m = 0; m < 16; m++) {
            float s0 = __shfl_sync(0xffffffffu, svA, m);
            float s1 = __shfl_sync(0xffffffffu, svA, m + 16);
            float s2 = __shfl_sync(0xffffffffu, svB, m);
            float s3 = __shfl_sync(0xffffffffu, svB, m + 16);
            float u0 = (m < 1) ? t00 : (m < 4) ? t01 : (m < 9) ? t02 : t03;
            float u1 = (m < 1) ? t10 : (m < 4) ? t11 : (m < 9) ? t12 : t13;
            float u2 = (m < 1) ? t20 : (m < 4) ? t21 : (m < 9) ? t22 : t23;
            float u3 = (m < 1) ? t30 : (m < 4) ? t31 : (m < 9) ? t32 : t33;
            acc[m] = fmaf(s0, u0, acc[m]);
            acc[m] = fmaf(s1, u1, acc[m]);
            acc[m] = fmaf(s2, u2, acc[m]);
            acc[m] = fmaf(s3, u3, acc[m]);
        }
        bA = nA; bB = nB;
    }
    for (; i < deg; i++) {                       // tail (<=3 edges)
        int2 en = __ldg(bk + i);
        edge_accum(acc, k, sh, rb, emb, en.x, en.y);
    }

    // Overflow edges for this atom (empty on this dataset: max deg ~60 << CAP).
    if (deg_raw > CAP) {
        int novf = g_ovf_count;
        if (novf > OVF_CAP) novf = OVF_CAP;
        for (int j = 0; j < novf; j++) {
            int e = g_ovf[j];
            if (centers[e] == a) edge_accum(acc, k, sh, rb, emb, e, neighbors[e]);
        }
    }

    // Streaming stores: out is write-once, never re-read.
    float* o = out + (size_t)a * 512 + k;
#pragma unroll
    for (int m = 0; m < 16; m++) __stcs(o + m * 32, acc[m] * MP_SCALING);

    // Restore scratch invariant for the next graph replay.
    if (k == 0) g_count[a] = 0;
}

// Persistent gather: each warp steals atoms from a global cursor, so no
// warp idles at block/wave boundaries waiting on a high-degree straggler.
__global__ __launch_bounds__(256) void gather_kernel(
    const float* __restrict__ sh, const float* __restrict__ rb,
    const float* __restrict__ emb,
    const int* __restrict__ centers, const int* __restrict__ neighbors,
    float* __restrict__ out, int n_atoms)
{
    int k = threadIdx.x & 31;
    for (;;) {
        int a = 0;
        if (k == 0) a = atomicAdd(&g_next, 1);
        a = __shfl_sync(0xffffffffu, a, 0);
        if (a >= n_atoms) break;
        process_atom(a, k, sh, rb, emb, centers, neighbors, out);
        if (a == 0 && k == 0) g_ovf_count = 0;
    }
}

extern "C" void kernel_launch(void* const* d_in, const int* in_sizes, int n_in,
                              void* d_out, int out_size) {
    const float* sh        = (const float*)d_in[0];  // (E, 16)
    const float* rb        = (const float*)d_in[1];  // (E, 4, 32)
    const float* emb       = (const float*)d_in[2];  // (n_atoms, 32)
    const int*   centers   = (const int*)d_in[3];    // (E,)
    const int*   neighbors = (const int*)d_in[4];    // (E,)
    float*       out       = (float*)d_out;          // (n_atoms, 16, 32)

    int E       = in_sizes[0] / 16;
    int n_atoms = in_sizes[2] / 32;

    scatter_kernel<<<(E / 4 + 511) / 512, 512>>>(centers, neighbors, E);
    // 444 blocks = 3 resident blocks/SM x 148 SMs: one persistent wave.
    gather_kernel<<<444, 256>>>(sh, rb, emb, centers, neighbors, out, n_atoms);
}

// round 13
// speedup vs baseline: 1.0362x; 1.0007x over previous
#include <cuda_runtime.h>

// Problem constants (shapes are fixed by the dataset).
#define N_ATOMS_C 20000
#define CAP 96          // per-atom bucket capacity; dataset max degree ~60
#define OVF_CAP 8192
#define MP_SCALING 0.1f
#define NBLK 444        // 3 blocks/SM x 148 SMs: all co-resident (grid barrier safe)

// Scratch: __device__ globals (no allocations allowed; zero-initialized at
// module load). All counters are restored to 0 by block 0 at kernel end,
// so every graph replay does identical work.
__device__ int  g_count[N_ATOMS_C];
__device__ int2 g_bucket[N_ATOMS_C * CAP];   // (edge_id, neighbor_id)
__device__ int  g_ovf_count;
__device__ int  g_ovf[OVF_CAP];
__device__ int  g_next;                      // gather work-stealing cursor
__device__ int  g_bar1;                      // scatter-done barrier
__device__ int  g_bar2;                      // exit barrier (guards reset)

__device__ __forceinline__ void scatter_one(int e, int c, int n) {
    int pos = atomicAdd(&g_count[c], 1);
    if (pos < CAP) {
        g_bucket[c * CAP + pos] = make_int2(e, n);
    } else {
        int o = atomicAdd(&g_ovf_count, 1);
        if (o < OVF_CAP) g_ovf[o] = e;
    }
}

// Single-edge accumulate (tail / overflow path).
__device__ __forceinline__ void edge_accum(
    float acc[16], int k,
    const float* __restrict__ sh,
    const float* __restrict__ rb,
    const float* __restrict__ emb,
    int e, int n)
{
    const float* rbe = rb + (size_t)e * 128 + k;
    float r0 = __ldcs(rbe), r1 = __ldcs(rbe + 32), r2 = __ldcs(rbe + 64), r3 = __ldcs(rbe + 96);
    float em = __ldg(emb + (size_t)n * 32 + k);
    float sv = (k < 16) ? __ldg(sh + (size_t)e * 16 + k) : 0.0f;
    float t0 = r0 * em, t1 = r1 * em, t2 = r2 * em, t3 = r3 * em;
#pragma unroll
    for (int m = 0; m < 16; m++) {
        float s = __shfl_sync(0xffffffffu, sv, m);
        float t = (m < 1) ? t0 : (m < 4) ? t1 : (m < 9) ? t2 : t3;
        acc[m] = fmaf(s, t, acc[m]);
    }
}

// One atom with the best-known body (4-edge unroll, bucket prefetch,
// evict-first rb loads, streaming out stores).
__device__ __forceinline__ void process_atom(
    int a, int k,
    const float* __restrict__ sh, const float* __restrict__ rb,
    const float* __restrict__ emb,
    const int* __restrict__ centers, const int* __restrict__ neighbors,
    float* __restrict__ out)
{
    int deg_raw = g_count[a];
    int deg = deg_raw > CAP ? CAP : deg_raw;

    float acc[16];
#pragma unroll
    for (int m = 0; m < 16; m++) acc[m] = 0.0f;

    const int2* bk = g_bucket + (size_t)a * CAP;

    int4 bA = make_int4(0,0,0,0), bB = bA;
    if (deg >= 4) {
        bA = __ldg((const int4*)bk);          // e0,n0,e1,n1
        bB = __ldg((const int4*)(bk + 2));    // e2,n2,e3,n3
    }

    int i = 0;
    for (; i + 4 <= deg; i += 4) {
        // Prefetch next group's bucket entries (L2 hit, hidden under compute).
        int4 nA = bA, nB = bB;
        if (i + 8 <= deg) {
            nA = __ldg((const int4*)(bk + i + 4));
            nB = __ldg((const int4*)(bk + i + 6));
        }

        // ---- front-batched load phase ----
        const float* p0 = rb + (size_t)bA.x * 128 + k;
        const float* p1 = rb + (size_t)bA.z * 128 + k;
        const float* p2 = rb + (size_t)bB.x * 128 + k;
        const float* p3 = rb + (size_t)bB.z * 128 + k;
        float r00=__ldcs(p0), r01=__ldcs(p0+32), r02=__ldcs(p0+64), r03=__ldcs(p0+96);
        float r10=__ldcs(p1), r11=__ldcs(p1+32), r12=__ldcs(p1+64), r13=__ldcs(p1+96);
        float r20=__ldcs(p2), r21=__ldcs(p2+32), r22=__ldcs(p2+64), r23=__ldcs(p2+96);
        float r30=__ldcs(p3), r31=__ldcs(p3+32), r32=__ldcs(p3+64), r33=__ldcs(p3+96);
        float em0 = __ldg(emb + (size_t)bA.y * 32 + k);
        float em1 = __ldg(emb + (size_t)bA.w * 32 + k);
        float em2 = __ldg(emb + (size_t)bB.y * 32 + k);
        float em3 = __ldg(emb + (size_t)bB.w * 32 + k);
        float svA = __ldg(sh + ((k < 16) ? (size_t)bA.x * 16 + k
                                         : (size_t)bA.z * 16 + (k - 16)));
        float svB = __ldg(sh + ((k < 16) ? (size_t)bB.x * 16 + k
                                         : (size_t)bB.z * 16 + (k - 16)));

        // ---- compute phase ----
        float t00=r00*em0, t01=r01*em0, t02=r02*em0, t03=r03*em0;
        float t10=r10*em1, t11=r11*em1, t12=r12*em1, t13=r13*em1;
        float t20=r20*em2, t21=r21*em2, t22=r22*em2, t23=r23*em2;
        float t30=r30*em3, t31=r31*em3, t32=r32*em3, t33=r33*em3;
#pragma unroll
        for (int m = 0; m < 16; m++) {
            float s0 = __shfl_sync(0xffffffffu, svA, m);
            float s1 = __shfl_sync(0xffffffffu, svA, m + 16);
            float s2 = __shfl_sync(0xffffffffu, svB, m);
            float s3 = __shfl_sync(0xffffffffu, svB, m + 16);
            float u0 = (m < 1) ? t00 : (m < 4) ? t01 : (m < 9) ? t02 : t03;
            float u1 = (m < 1) ? t10 : (m < 4) ? t11 : (m < 9) ? t12 : t13;
            float u2 = (m < 1) ? t20 : (m < 4) ? t21 : (m < 9) ? t22 : t23;
            float u3 = (m < 1) ? t30 : (m < 4) ? t31 : (m < 9) ? t32 : t33;
            acc[m] = fmaf(s0, u0, acc[m]);
            acc[m] = fmaf(s1, u1, acc[m]);
            acc[m] = fmaf(s2, u2, acc[m]);
            acc[m] = fmaf(s3, u3, acc[m]);
        }
        bA = nA; bB = nB;
    }
    for (; i < deg; i++) {                       // tail (<=3 edges)
        int2 en = __ldg(bk + i);
        edge_accum(acc, k, sh, rb, emb, en.x, en.y);
    }

    // Overflow edges for this atom (empty on this dataset: max deg ~60 << CAP).
    if (deg_raw > CAP) {
        int novf = g_ovf_count;
        if (novf > OVF_CAP) novf = OVF_CAP;
        for (int j = 0; j < novf; j++) {
            int e = g_ovf[j];
            if (centers[e] == a) edge_accum(acc, k, sh, rb, emb, e, neighbors[e]);
        }
    }

    // Streaming stores: out is write-once, never re-read.
    float* o = out + (size_t)a * 512 + k;
#pragma unroll
    for (int m = 0; m < 16; m++) __stcs(o + m * 32, acc[m] * MP_SCALING);

    // Restore scratch invariant for the next graph replay.
    if (k == 0) g_count[a] = 0;
}

// Fused persistent kernel: scatter phase -> grid barrier -> work-stealing
// gather phase -> exit barrier -> block 0 resets all cursors.
// __launch_bounds__(256, 3) caps regs at 85 so 3 blocks/SM (= all 444)
// are co-resident, making the software grid barrier deadlock-free.
__global__ __launch_bounds__(256, 3) void fused_kernel(
    const float* __restrict__ sh, const float* __restrict__ rb,
    const float* __restrict__ emb,
    const int* __restrict__ centers, const int* __restrict__ neighbors,
    float* __restrict__ out, int E, int n_atoms)
{
    // ---------------- scatter phase ----------------
    int nth = gridDim.x * blockDim.x;
    int t0  = blockIdx.x * blockDim.x + threadIdx.x;
    for (int e = t0 * 4; e < E; e += nth * 4) {
        if (e + 3 < E) {
            int4 c = __ldg((const int4*)(centers + e));
            int4 n = __ldg((const int4*)(neighbors + e));
            scatter_one(e,     c.x, n.x);
            scatter_one(e + 1, c.y, n.y);
            scatter_one(e + 2, c.z, n.z);
            scatter_one(e + 3, c.w, n.w);
        } else {
            for (int j = e; j < E; j++) scatter_one(j, centers[j], neighbors[j]);
        }
    }

    // ---------------- grid barrier (release/acquire) ----------------
    __syncthreads();
    __threadfence();                          // publish bucket/count stores
    if (threadIdx.x == 0) {
        atomicAdd(&g_bar1, 1);
        while (*((volatile int*)&g_bar1) < (int)gridDim.x) { }
    }
    __syncthreads();
    __threadfence();                          // acquire

    // ---------------- gather phase (work-stealing) ----------------
    int k = threadIdx.x & 31;
    for (;;) {
        int a = 0;
        if (k == 0) a = atomicAdd(&g_next, 1);
        a = __shfl_sync(0xffffffffu, a, 0);
        if (a >= n_atoms) break;
        process_atom(a, k, sh, rb, emb, centers, neighbors, out);
    }

    // ---------------- exit barrier + state reset ----------------
    __syncthreads();
    if (threadIdx.x == 0) {
        __threadfence();
        atomicAdd(&g_bar2, 1);
        if (blockIdx.x == 0) {
            while (*((volatile int*)&g_bar2) < (int)gridDim.x) { }
            g_bar1 = 0;
            g_bar2 = 0;
            g_next = 0;
            g_ovf_count = 0;
            __threadfence();
        }
    }
}

extern "C" void kernel_launch(void* const* d_in, const int* in_sizes, int n_in,
                              void* d_out, int out_size) {
    const float* sh        = (const float*)d_in[0];  // (E, 16)
    const float* rb        = (const float*)d_in[1];  // (E, 4, 32)
    const float* emb       = (const float*)d_in[2];  // (n_atoms, 32)
    const int*   centers   = (const int*)d_in[3];    // (E,)
    const int*   neighbors = (const int*)d_in[4];    // (E,)
    float*       out       = (float*)d_out;          // (n_atoms, 16, 32)

    int E       = in_sizes[0] / 16;
    int n_atoms = in_sizes[2] / 32;

    fused_kernel<<<NBLK, 256>>>(sh, rb, emb, centers, neighbors, out,
                                E, n_atoms);
}

// round 14
// speedup vs baseline: 1.0512x; 1.0145x over previous
#include <cuda_runtime.h>

// Problem constants (shapes are fixed by the dataset).
#define N_ATOMS_C 20000
#define CAP 96          // per-atom bucket capacity; dataset max degree ~60
#define OVF_CAP 8192
#define MP_SCALING 0.1f

// Scratch: __device__ globals (no allocations allowed; zero-initialized at
// module load). Invariant: g_count/g_ovf_count are 0 on entry to
// kernel_launch and restored to 0 by gather_kernel, so every call does
// identical work.
__device__ int  g_count[N_ATOMS_C];
__device__ int2 g_bucket[N_ATOMS_C * CAP];   // (edge_id, neighbor_id)
__device__ int  g_ovf_count;
__device__ int  g_ovf[OVF_CAP];

__device__ __forceinline__ void scatter_one(int e, int c, int n) {
    int pos = atomicAdd(&g_count[c], 1);
    if (pos < CAP) {
        g_bucket[c * CAP + pos] = make_int2(e, n);
    } else {
        int o = atomicAdd(&g_ovf_count, 1);
        if (o < OVF_CAP) g_ovf[o] = e;
    }
}

// 8 edges per thread: 8 independent atomic->store chains in flight hides
// the ~318-cycle L2 atomic return latency better; half the threads.
__global__ void scatter_kernel(const int* __restrict__ centers,
                               const int* __restrict__ neighbors, int E) {
    int t = blockIdx.x * blockDim.x + threadIdx.x;
    int e = t * 8;
    if (e + 7 < E) {
        int4 c0 = __ldg((const int4*)(centers + e));
        int4 c1 = __ldg((const int4*)(centers + e + 4));
        int4 n0 = __ldg((const int4*)(neighbors + e));
        int4 n1 = __ldg((const int4*)(neighbors + e + 4));
        scatter_one(e,     c0.x, n0.x);
        scatter_one(e + 1, c0.y, n0.y);
        scatter_one(e + 2, c0.z, n0.z);
        scatter_one(e + 3, c0.w, n0.w);
        scatter_one(e + 4, c1.x, n1.x);
        scatter_one(e + 5, c1.y, n1.y);
        scatter_one(e + 6, c1.z, n1.z);
        scatter_one(e + 7, c1.w, n1.w);
    } else {
        for (int j = e; j < E; j++) scatter_one(j, centers[j], neighbors[j]);
    }
}

// Single-edge accumulate (tail / overflow path).
__device__ __forceinline__ void edge_accum(
    float acc[16], int k,
    const float* __restrict__ sh,
    const float* __restrict__ rb,
    const float* __restrict__ emb,
    int e, int n)
{
    const float* rbe = rb + (size_t)e * 128 + k;
    float r0 = __ldcs(rbe), r1 = __ldcs(rbe + 32), r2 = __ldcs(rbe + 64), r3 = __ldcs(rbe + 96);
    float em = __ldg(emb + (size_t)n * 32 + k);
    float sv = (k < 16) ? __ldg(sh + (size_t)e * 16 + k) : 0.0f;
    float t0 = r0 * em, t1 = r1 * em, t2 = r2 * em, t3 = r3 * em;
#pragma unroll
    for (int m = 0; m < 16; m++) {
        float s = __shfl_sync(0xffffffffu, sv, m);
        float t = (m < 1) ? t0 : (m < 4) ? t1 : (m < 9) ? t2 : t3;
        acc[m] = fmaf(s, t, acc[m]);
    }
}

// One warp per atom; lane = k. Byte-identical to the best-measured (R10)
// body: 4-edge unroll, bucket prefetch, evict-first rb loads, streaming
// stores. PDL: launched with programmatic stream serialization; syncs on
// the grid dependency before reading any scatter output.
__global__ __launch_bounds__(256) void gather_kernel(
    const float* __restrict__ sh, const float* __restrict__ rb,
    const float* __restrict__ emb,
    const int* __restrict__ centers, const int* __restrict__ neighbors,
    float* __restrict__ out, int n_atoms)
{
    // Wait for the scatter kernel's results (PDL overlap of launch/setup).
    cudaGridDependencySynchronize();

    int a = blockIdx.x * 8 + (threadIdx.x >> 5);
    if (a >= n_atoms) return;
    int k = threadIdx.x & 31;

    int deg_raw = g_count[a];
    int deg = deg_raw > CAP ? CAP : deg_raw;

    float acc[16];
#pragma unroll
    for (int m = 0; m < 16; m++) acc[m] = 0.0f;

    const int2* bk = g_bucket + (size_t)a * CAP;

    int4 bA = make_int4(0,0,0,0), bB = bA;
    if (deg >= 4) {
        bA = __ldg((const int4*)bk);          // e0,n0,e1,n1
        bB = __ldg((const int4*)(bk + 2));    // e2,n2,e3,n3
    }

    int i = 0;
    for (; i + 4 <= deg; i += 4) {
        // Prefetch next group's bucket entries (L2 hit, hidden under compute).
        int4 nA = bA, nB = bB;
        if (i + 8 <= deg) {
            nA = __ldg((const int4*)(bk + i + 4));
            nB = __ldg((const int4*)(bk + i + 6));
        }

        // ---- front-batched load phase ----
        const float* p0 = rb + (size_t)bA.x * 128 + k;
        const float* p1 = rb + (size_t)bA.z * 128 + k;
        const float* p2 = rb + (size_t)bB.x * 128 + k;
        const float* p3 = rb + (size_t)bB.z * 128 + k;
        float r00=__ldcs(p0), r01=__ldcs(p0+32), r02=__ldcs(p0+64), r03=__ldcs(p0+96);
        float r10=__ldcs(p1), r11=__ldcs(p1+32), r12=__ldcs(p1+64), r13=__ldcs(p1+96);
        float r20=__ldcs(p2), r21=__ldcs(p2+32), r22=__ldcs(p2+64), r23=__ldcs(p2+96);
        float r30=__ldcs(p3), r31=__ldcs(p3+32), r32=__ldcs(p3+64), r33=__ldcs(p3+96);
        float em0 = __ldg(emb + (size_t)bA.y * 32 + k);
        float em1 = __ldg(emb + (size_t)bA.w * 32 + k);
        float em2 = __ldg(emb + (size_t)bB.y * 32 + k);
        float em3 = __ldg(emb + (size_t)bB.w * 32 + k);
        float svA = __ldg(sh + ((k < 16) ? (size_t)bA.x * 16 + k
                                         : (size_t)bA.z * 16 + (k - 16)));
        float svB = __ldg(sh + ((k < 16) ? (size_t)bB.x * 16 + k
                                         : (size_t)bB.z * 16 + (k - 16)));

        // ---- compute phase ----
        float t00=r00*em0, t01=r01*em0, t02=r02*em0, t03=r03*em0;
        float t10=r10*em1, t11=r11*em1, t12=r12*em1, t13=r13*em1;
        float t20=r20*em2, t21=r21*em2, t22=r22*em2, t23=r23*em2;
        float t30=r30*em3, t31=r31*em3, t32=r32*em3, t33=r33*em3;
#pragma unroll
        for (int m = 0; m < 16; m++) {
            float s0 = __shfl_sync(0xffffffffu, svA, m);
            float s1 = __shfl_sync(0xffffffffu, svA, m + 16);
            float s2 = __shfl_sync(0xffffffffu, svB, m);
            float s3 = __shfl_sync(0xffffffffu, svB, m + 16);
            float u0 = (m < 1) ? t00 : (m < 4) ? t01 : (m < 9) ? t02 : t03;
            float u1 = (m < 1) ? t10 : (m < 4) ? t11 : (m < 9) ? t12 : t13;
            float u2 = (m < 1) ? t20 : (m < 4) ? t21 : (m < 9) ? t22 : t23;
            float u3 = (m < 1) ? t30 : (m < 4) ? t31 : (m < 9) ? t32 : t33;
            acc[m] = fmaf(s0, u0, acc[m]);
            acc[m] = fmaf(s1, u1, acc[m]);
            acc[m] = fmaf(s2, u2, acc[m]);
            acc[m] = fmaf(s3, u3, acc[m]);
        }
        bA = nA; bB = nB;
    }
    for (; i < deg; i++) {                       // tail (<=3 edges)
        int2 en = __ldg(bk + i);
        edge_accum(acc, k, sh, rb, emb, en.x, en.y);
    }

    // Overflow edges for this atom (empty on this dataset: max deg ~60 << CAP).
    if (deg_raw > CAP) {
        int novf = g_ovf_count;
        if (novf > OVF_CAP) novf = OVF_CAP;
        for (int j = 0; j < novf; j++) {
            int e = g_ovf[j];
            if (centers[e] == a) edge_accum(acc, k, sh, rb, emb, e, neighbors[e]);
        }
    }

    // Streaming stores: out is write-once, never re-read.
    float* o = out + (size_t)a * 512 + k;
#pragma unroll
    for (int m = 0; m < 16; m++) __stcs(o + m * 32, acc[m] * MP_SCALING);

    // Restore scratch invariant for the next graph replay.
    if (k == 0) g_count[a] = 0;
    if (a == 0 && k == 0) g_ovf_count = 0;
}

extern "C" void kernel_launch(void* const* d_in, const int* in_sizes, int n_in,
                              void* d_out, int out_size) {
    const float* sh        = (const float*)d_in[0];  // (E, 16)
    const float* rb        = (const float*)d_in[1];  // (E, 4, 32)
    const float* emb       = (const float*)d_in[2];  // (n_atoms, 32)
    const int*   centers   = (const int*)d_in[3];    // (E,)
    const int*   neighbors = (const int*)d_in[4];    // (E,)
    float*       out       = (float*)d_out;          // (n_atoms, 16, 32)

    int E       = in_sizes[0] / 16;
    int n_atoms = in_sizes[2] / 32;

    scatter_kernel<<<(E / 8 + 511) / 512, 512>>>(centers, neighbors, E);

    // Gather with programmatic dependent launch: its launch/setup overlaps
    // the scatter tail; cudaGridDependencySynchronize() inside the kernel
    // enforces the data dependency. Falls back to normal stream ordering
    // if the attribute is unsupported.
    cudaLaunchConfig_t cfg = {};
    cfg.gridDim  = dim3((unsigned)((n_atoms + 7) / 8), 1, 1);
    cfg.blockDim = dim3(256, 1, 1);
    cfg.dynamicSmemBytes = 0;
    cfg.stream = 0;                       // legacy default stream (captured)
    cudaLaunchAttribute attrs[1];
    attrs[0].id = cudaLaunchAttributeProgrammaticStreamSerialization;
    attrs[0].val.programmaticStreamSerializationAllowed = 1;
    cfg.attrs = attrs;
    cfg.numAttrs = 1;
    cudaLaunchKernelEx(&cfg, gather_kernel, sh, rb, emb, centers, neighbors,
                       (float*)d_out, n_atoms);
}

// round 15
// speedup vs baseline: 1.0541x; 1.0027x over previous
#include <cuda_runtime.h>

// Problem constants (shapes are fixed by the dataset).
#define N_ATOMS_C 20000
#define CAP 96          // per-atom bucket capacity; dataset max degree ~60
#define OVF_CAP 8192
#define MP_SCALING 0.1f

// Scratch: __device__ globals (no allocations allowed; zero-initialized at
// module load). Invariant: g_count/g_ovf_count are 0 on entry to
// kernel_launch and restored to 0 by gather_kernel, so every call does
// identical work.
__device__ int  g_count[N_ATOMS_C];
__device__ int2 g_bucket[N_ATOMS_C * CAP];   // (edge_id, neighbor_id)
__device__ int  g_ovf_count;
__device__ int  g_ovf[OVF_CAP];

__device__ __forceinline__ void scatter_one(int e, int c, int n) {
    int pos = atomicAdd(&g_count[c], 1);
    if (pos < CAP) {
        g_bucket[c * CAP + pos] = make_int2(e, n);
    } else {
        int o = atomicAdd(&g_ovf_count, 1);
        if (o < OVF_CAP) g_ovf[o] = e;
    }
}

// 4 edges per thread, 256-thread blocks: 625 blocks gives finer wave
// granularity for the tail drain than 313x512.
__global__ void scatter_kernel(const int* __restrict__ centers,
                               const int* __restrict__ neighbors, int E) {
    int t = blockIdx.x * blockDim.x + threadIdx.x;
    int e = t * 4;
    if (e + 3 < E) {
        int4 c = __ldg((const int4*)(centers + e));
        int4 n = __ldg((const int4*)(neighbors + e));
        scatter_one(e,     c.x, n.x);
        scatter_one(e + 1, c.y, n.y);
        scatter_one(e + 2, c.z, n.z);
        scatter_one(e + 3, c.w, n.w);
    } else {
        for (int j = e; j < E; j++) scatter_one(j, centers[j], neighbors[j]);
    }
}

// Single-edge accumulate (tail / overflow path).
__device__ __forceinline__ void edge_accum(
    float acc[16], int k,
    const float* __restrict__ sh,
    const float* __restrict__ rb,
    const float* __restrict__ emb,
    int e, int n)
{
    const float* rbe = rb + (size_t)e * 128 + k;
    float r0 = __ldcs(rbe), r1 = __ldcs(rbe + 32), r2 = __ldcs(rbe + 64), r3 = __ldcs(rbe + 96);
    float em = __ldg(emb + (size_t)n * 32 + k);
    float sv = (k < 16) ? __ldg(sh + (size_t)e * 16 + k) : 0.0f;
    float t0 = r0 * em, t1 = r1 * em, t2 = r2 * em, t3 = r3 * em;
#pragma unroll
    for (int m = 0; m < 16; m++) {
        float s = __shfl_sync(0xffffffffu, sv, m);
        float t = (m < 1) ? t0 : (m < 4) ? t1 : (m < 9) ? t2 : t3;
        acc[m] = fmaf(s, t, acc[m]);
    }
}

// One warp per atom; lane = k. Champion body (R10): 4-edge unroll with 24
// front-batched LDGs/group, next group's bucket entries prefetched during
// compute, evict-first rb loads, streaming out stores.
__global__ __launch_bounds__(256) void gather_kernel(
    const float* __restrict__ sh, const float* __restrict__ rb,
    const float* __restrict__ emb,
    const int* __restrict__ centers, const int* __restrict__ neighbors,
    float* __restrict__ out, int n_atoms)
{
    int a = blockIdx.x * 8 + (threadIdx.x >> 5);
    if (a >= n_atoms) return;
    int k = threadIdx.x & 31;

    int deg_raw = g_count[a];
    int deg = deg_raw > CAP ? CAP : deg_raw;

    float acc[16];
#pragma unroll
    for (int m = 0; m < 16; m++) acc[m] = 0.0f;

    const int2* bk = g_bucket + (size_t)a * CAP;

    int4 bA = make_int4(0,0,0,0), bB = bA;
    if (deg >= 4) {
        bA = __ldg((const int4*)bk);          // e0,n0,e1,n1
        bB = __ldg((const int4*)(bk + 2));    // e2,n2,e3,n3
    }

    int i = 0;
    for (; i + 4 <= deg; i += 4) {
        // Prefetch next group's bucket entries (L2 hit, hidden under compute).
        int4 nA = bA, nB = bB;
        if (i + 8 <= deg) {
            nA = __ldg((const int4*)(bk + i + 4));
            nB = __ldg((const int4*)(bk + i + 6));
        }

        // ---- front-batched load phase ----
        const float* p0 = rb + (size_t)bA.x * 128 + k;
        const float* p1 = rb + (size_t)bA.z * 128 + k;
        const float* p2 = rb + (size_t)bB.x * 128 + k;
        const float* p3 = rb + (size_t)bB.z * 128 + k;
        float r00=__ldcs(p0), r01=__ldcs(p0+32), r02=__ldcs(p0+64), r03=__ldcs(p0+96);
        float r10=__ldcs(p1), r11=__ldcs(p1+32), r12=__ldcs(p1+64), r13=__ldcs(p1+96);
        float r20=__ldcs(p2), r21=__ldcs(p2+32), r22=__ldcs(p2+64), r23=__ldcs(p2+96);
        float r30=__ldcs(p3), r31=__ldcs(p3+32), r32=__ldcs(p3+64), r33=__ldcs(p3+96);
        float em0 = __ldg(emb + (size_t)bA.y * 32 + k);
        float em1 = __ldg(emb + (size_t)bA.w * 32 + k);
        float em2 = __ldg(emb + (size_t)bB.y * 32 + k);
        float em3 = __ldg(emb + (size_t)bB.w * 32 + k);
        float svA = __ldg(sh + ((k < 16) ? (size_t)bA.x * 16 + k
                                         : (size_t)bA.z * 16 + (k - 16)));
        float svB = __ldg(sh + ((k < 16) ? (size_t)bB.x * 16 + k
                                         : (size_t)bB.z * 16 + (k - 16)));

        // ---- compute phase ----
        float t00=r00*em0, t01=r01*em0, t02=r02*em0, t03=r03*em0;
        float t10=r10*em1, t11=r11*em1, t12=r12*em1, t13=r13*em1;
        float t20=r20*em2, t21=r21*em2, t22=r22*em2, t23=r23*em2;
        float t30=r30*em3, t31=r31*em3, t32=r32*em3, t33=r33*em3;
#pragma unroll
        for (int m = 0; m < 16; m++) {
            float s0 = __shfl_sync(0xffffffffu, svA, m);
            float s1 = __shfl_sync(0xffffffffu, svA, m + 16);
            float s2 = __shfl_sync(0xffffffffu, svB, m);
            float s3 = __shfl_sync(0xffffffffu, svB, m + 16);
            float u0 = (m < 1) ? t00 : (m < 4) ? t01 : (m < 9) ? t02 : t03;
            float u1 = (m < 1) ? t10 : (m < 4) ? t11 : (m < 9) ? t12 : t13;
            float u2 = (m < 1) ? t20 : (m < 4) ? t21 : (m < 9) ? t22 : t23;
            float u3 = (m < 1) ? t30 : (m < 4) ? t31 : (m < 9) ? t32 : t33;
            acc[m] = fmaf(s0, u0, acc[m]);
            acc[m] = fmaf(s1, u1, acc[m]);
            acc[m] = fmaf(s2, u2, acc[m]);
            acc[m] = fmaf(s3, u3, acc[m]);
        }
        bA = nA; bB = nB;
    }
    for (; i < deg; i++) {                       // tail (<=3 edges)
        int2 en = __ldg(bk + i);
        edge_accum(acc, k, sh, rb, emb, en.x, en.y);
    }

    // Overflow edges for this atom (empty on this dataset: max deg ~60 << CAP).
    if (deg_raw > CAP) {
        int novf = g_ovf_count;
        if (novf > OVF_CAP) novf = OVF_CAP;
        for (int j = 0; j < novf; j++) {
            int e = g_ovf[j];
            if (centers[e] == a) edge_accum(acc, k, sh, rb, emb, e, neighbors[e]);
        }
    }

    // Streaming stores: out is write-once, never re-read.
    float* o = out + (size_t)a * 512 + k;
#pragma unroll
    for (int m = 0; m < 16; m++) __stcs(o + m * 32, acc[m] * MP_SCALING);

    // Restore scratch invariant for the next graph replay.
    if (k == 0) g_count[a] = 0;
    if (a == 0 && k == 0) g_ovf_count = 0;
}

extern "C" void kernel_launch(void* const* d_in, const int* in_sizes, int n_in,
                              void* d_out, int out_size) {
    const float* sh        = (const float*)d_in[0];  // (E, 16)
    const float* rb        = (const float*)d_in[1];  // (E, 4, 32)
    const float* emb       = (const float*)d_in[2];  // (n_atoms, 32)
    const int*   centers   = (const int*)d_in[3];    // (E,)
    const int*   neighbors = (const int*)d_in[4];    // (E,)
    float*       out       = (float*)d_out;          // (n_atoms, 16, 32)

    int E       = in_sizes[0] / 16;
    int n_atoms = in_sizes[2] / 32;

    scatter_kernel<<<(E / 4 + 255) / 256, 256>>>(centers, neighbors, E);
    gather_kernel<<<(n_atoms + 7) / 8, 256>>>(sh, rb, emb, centers, neighbors,
                                              out, n_atoms);
}